// round 9
// baseline (speedup 1.0000x reference)
#include <cuda_runtime.h>
#include <cuda_bf16.h>

// Problem constants (fixed shapes per reference)
#define NN 100000
#define EE 600000
#define HH 128
#define GG 4000
#define TT 128

// Scratch (allocation-free: device globals)
__device__ float g_deg[NN];                 // degree, then dinv in-place
__device__ float g_h[(size_t)NN * HH];
__device__ float g_t[(size_t)NN * HH];
__device__ float g_o[(size_t)NN * HH];
__device__ float g_pool[(size_t)GG * HH];
__device__ float g_cnt[GG];

__constant__ int c_off[9] = {0, 119, 124, 136, 148, 158, 164, 170, 172};

// ---------------------------------------------------------------------------
__global__ void deg_init_kernel() {
    int i = blockIdx.x * blockDim.x + threadIdx.x;
    if (i < NN) g_deg[i] = 1.0f;
}

__global__ void deg_scatter_kernel(const int* __restrict__ dst) {
    int e = blockIdx.x * blockDim.x + threadIdx.x;
    if (e < EE) atomicAdd(&g_deg[dst[e]], 1.0f);
}

// AtomEncoder: h[n] = sum_f emb[x[n,f]+off[f]]; also deg -> dinv in place.
__global__ void embed_kernel(const int* __restrict__ x, const float* __restrict__ emb) {
    int n = blockIdx.x;
    int t = threadIdx.x;
    __shared__ int xi[9];
    if (t < 9) xi[t] = x[n * 9 + t] + c_off[t];
    __syncthreads();
    float v = 0.0f;
#pragma unroll
    for (int f = 0; f < 9; f++) v += emb[(size_t)xi[f] * HH + t];
    g_h[(size_t)n * HH + t] = v;
    if (t == 0) g_deg[n] = rsqrtf(g_deg[n]);
}

// ---------------------------------------------------------------------------
// GEMM: C[M,128] = A'[M,128] @ B[128,128]
// MODE 0: layer, A as-is.  MODE 1: layer, relu(A).  MODE 2: final, A/max(cnt,1).
// Layer epilogue: T = A'@B ; OUT = dinv^2 * T + bias   (self-loop init)
// Final epilogue: OUT = A'@B + bias
//
// Whole A tile (128x128) and whole B (128x128) resident in 128KB dynamic smem.
// Single __syncthreads; inner loop uses packed fma.rn.f32x2 (2 MACs/lane/instr,
// bit-identical rounding to scalar FFMA).
template <int MODE>
__global__ void __launch_bounds__(256, 1)
gemm_kernel(const float* __restrict__ A, const float* __restrict__ B,
            const float* __restrict__ bias, float* __restrict__ T,
            float* __restrict__ OUT, int M) {
    extern __shared__ float sm[];
    float* Bs = sm;             // [k][col], 128x128
    float* As = sm + 16384;     // [row][k], 128x128 (row-major like global)

    const int tid = threadIdx.x;            // 256 threads
    const int row0 = blockIdx.x * 128;

    // Stage B: coalesced, conflict-free.
#pragma unroll
    for (int i = tid; i < 4096; i += 256) {
        const int r = i >> 5, c = (i & 31) << 2;
        *(float4*)&Bs[r * 128 + c] = *(const float4*)&B[r * 128 + c];
    }
    // Stage A (row-major) with MODE transform fused.
#pragma unroll
    for (int i = tid; i < 4096; i += 256) {
        const int r = i >> 5, c = (i & 31) << 2;
        const int gr = row0 + r;
        float4 v = make_float4(0.f, 0.f, 0.f, 0.f);
        if (gr < M) v = *(const float4*)&A[(size_t)gr * HH + c];
        if (MODE == 1) {
            v.x = fmaxf(v.x, 0.f); v.y = fmaxf(v.y, 0.f);
            v.z = fmaxf(v.z, 0.f); v.w = fmaxf(v.w, 0.f);
        }
        if (MODE == 2) {
            const float ps = (gr < M) ? 1.0f / fmaxf(g_cnt[gr], 1.0f) : 0.0f;
            v.x *= ps; v.y *= ps; v.z *= ps; v.w *= ps;
        }
        *(float4*)&As[r * 128 + c] = v;
    }
    __syncthreads();

    const int tx = tid & 15;                 // 16 col groups
    const int ty = tid >> 4;                 // 16 row groups
    const int c0 = tx << 3;                  // 8 cols / thread
    const int r0t = ty << 3;                 // 8 rows / thread

    unsigned long long acc[8][4];            // 8 rows x 4 packed f32x2 col-pairs
#pragma unroll
    for (int i = 0; i < 8; i++)
#pragma unroll
        for (int j = 0; j < 4; j++) acc[i][j] = 0ull;

#pragma unroll 4
    for (int k = 0; k < 128; k++) {
        // B fragment: 8 cols = 4 packed pairs (little-endian: low half = even col)
        const ulonglong2 b01 = *(const ulonglong2*)&Bs[k * 128 + c0];
        const ulonglong2 b23 = *(const ulonglong2*)&Bs[k * 128 + c0 + 4];
        unsigned long long bb[4];
        bb[0] = b01.x; bb[1] = b01.y; bb[2] = b23.x; bb[3] = b23.y;
#pragma unroll
        for (int i = 0; i < 8; i++) {
            const float a = As[(r0t + i) * 128 + k];   // 16-lane broadcast LDS
            unsigned long long a2;
            asm("mov.b64 %0, {%1, %1};" : "=l"(a2) : "f"(a));
#pragma unroll
            for (int j = 0; j < 4; j++)
                asm("fma.rn.f32x2 %0, %1, %2, %0;" : "+l"(acc[i][j]) : "l"(a2), "l"(bb[j]));
        }
    }

    // bias fragment
    float bsv[8];
    {
        const float4 bl0 = *(const float4*)&bias[c0];
        const float4 bl1 = *(const float4*)&bias[c0 + 4];
        bsv[0] = bl0.x; bsv[1] = bl0.y; bsv[2] = bl0.z; bsv[3] = bl0.w;
        bsv[4] = bl1.x; bsv[5] = bl1.y; bsv[6] = bl1.z; bsv[7] = bl1.w;
    }

#pragma unroll
    for (int i = 0; i < 8; i++) {
        const int r = row0 + r0t + i;
        if (r >= M) continue;
        float v[8];
#pragma unroll
        for (int j = 0; j < 4; j++)
            asm("mov.b64 {%0, %1}, %2;" : "=f"(v[2 * j]), "=f"(v[2 * j + 1]) : "l"(acc[i][j]));
        if (MODE == 2) {
            float4 o0, o1;
            o0.x = v[0] + bsv[0]; o0.y = v[1] + bsv[1]; o0.z = v[2] + bsv[2]; o0.w = v[3] + bsv[3];
            o1.x = v[4] + bsv[4]; o1.y = v[5] + bsv[5]; o1.z = v[6] + bsv[6]; o1.w = v[7] + bsv[7];
            *(float4*)&OUT[(size_t)r * TT + c0] = o0;
            *(float4*)&OUT[(size_t)r * TT + c0 + 4] = o1;
        } else {
            const float d = g_deg[r];   // dinv
            const float d2 = d * d;
            float4 t0, t1, o0, o1;
            t0.x = v[0]; t0.y = v[1]; t0.z = v[2]; t0.w = v[3];
            t1.x = v[4]; t1.y = v[5]; t1.z = v[6]; t1.w = v[7];
            o0.x = fmaf(d2, v[0], bsv[0]); o0.y = fmaf(d2, v[1], bsv[1]);
            o0.z = fmaf(d2, v[2], bsv[2]); o0.w = fmaf(d2, v[3], bsv[3]);
            o1.x = fmaf(d2, v[4], bsv[4]); o1.y = fmaf(d2, v[5], bsv[5]);
            o1.z = fmaf(d2, v[6], bsv[6]); o1.w = fmaf(d2, v[7], bsv[7]);
            *(float4*)&T[(size_t)r * HH + c0] = t0;
            *(float4*)&T[(size_t)r * HH + c0 + 4] = t1;
            *(float4*)&OUT[(size_t)r * HH + c0] = o0;
            *(float4*)&OUT[(size_t)r * HH + c0 + 4] = o1;
        }
    }
}

// ---------------------------------------------------------------------------
// Edge scatter: out[dst] += t[src] * dinv[src] * dinv[dst]   (one warp / edge)
__global__ void edge_kernel(const int* __restrict__ src, const int* __restrict__ dst,
                            const float* __restrict__ t, float* __restrict__ out) {
    const int w = (blockIdx.x * blockDim.x + threadIdx.x) >> 5;
    const int lane = threadIdx.x & 31;
    if (w >= EE) return;
    const int s = src[w];
    const int d = dst[w];
    const float c = g_deg[s] * g_deg[d];
    float4 v = *(const float4*)(t + (size_t)s * HH + (lane << 2));
    v.x *= c; v.y *= c; v.z *= c; v.w *= c;
    float* p = out + (size_t)d * HH + (lane << 2);
    asm volatile("red.global.add.v4.f32 [%0], {%1,%2,%3,%4};"
                 :: "l"(p), "f"(v.x), "f"(v.y), "f"(v.z), "f"(v.w)
                 : "memory");
}

// ---------------------------------------------------------------------------
__global__ void pool_zero_kernel() {
    int i = blockIdx.x * blockDim.x + threadIdx.x;
    if (i < GG * HH) g_pool[i] = 0.0f;
    if (i < GG) g_cnt[i] = 0.0f;
}

// one warp / node: pooled[batch[n]] += h[n]; cnt[batch[n]] += 1
__global__ void pool_scatter_kernel(const int* __restrict__ batch, const float* __restrict__ h) {
    const int n = (blockIdx.x * blockDim.x + threadIdx.x) >> 5;
    const int lane = threadIdx.x & 31;
    if (n >= NN) return;
    const int g = batch[n];
    float4 v = *(const float4*)(h + (size_t)n * HH + (lane << 2));
    float* p = g_pool + (size_t)g * HH + (lane << 2);
    asm volatile("red.global.add.v4.f32 [%0], {%1,%2,%3,%4};"
                 :: "l"(p), "f"(v.x), "f"(v.y), "f"(v.z), "f"(v.w)
                 : "memory");
    if (lane == 0) atomicAdd(&g_cnt[g], 1.0f);
}

// ---------------------------------------------------------------------------
extern "C" void kernel_launch(void* const* d_in, const int* in_sizes, int n_in,
                              void* d_out, int out_size) {
    const int*   x     = (const int*)d_in[0];
    const int*   ei    = (const int*)d_in[1];
    const int*   batch = (const int*)d_in[2];
    const float* emb   = (const float*)d_in[3];
    const float* W1    = (const float*)d_in[4];
    const float* b1    = (const float*)d_in[5];
    const float* W2    = (const float*)d_in[6];
    const float* b2    = (const float*)d_in[7];
    const float* W3    = (const float*)d_in[8];
    const float* b3    = (const float*)d_in[9];
    const float* Wl    = (const float*)d_in[10];
    const float* bl    = (const float*)d_in[11];
    float* out = (float*)d_out;

    const int* srcp = ei;
    const int* dstp = ei + EE;

    float *p_h, *p_t, *p_o, *p_pool;
    cudaGetSymbolAddress((void**)&p_h, g_h);
    cudaGetSymbolAddress((void**)&p_t, g_t);
    cudaGetSymbolAddress((void**)&p_o, g_o);
    cudaGetSymbolAddress((void**)&p_pool, g_pool);

    const int SMEM = 2 * 128 * 128 * (int)sizeof(float);   // 128KB dynamic smem
    static bool attr_set = false;
    if (!attr_set) {
        cudaFuncSetAttribute(gemm_kernel<0>, cudaFuncAttributeMaxDynamicSharedMemorySize, SMEM);
        cudaFuncSetAttribute(gemm_kernel<1>, cudaFuncAttributeMaxDynamicSharedMemorySize, SMEM);
        cudaFuncSetAttribute(gemm_kernel<2>, cudaFuncAttributeMaxDynamicSharedMemorySize, SMEM);
        attr_set = true;
    }

    // degree (with self-loop) -> dinv
    deg_init_kernel<<<(NN + 255) / 256, 256>>>();
    deg_scatter_kernel<<<(EE + 255) / 256, 256>>>(dstp);

    // atom embedding sum + dinv conversion
    embed_kernel<<<NN, 128>>>(x, emb);

    const int gemm_blocks = (NN + 127) / 128;
    const int edge_blocks = (EE * 32 + 255) / 256;

    // Layer 1: h -> t; o = dinv^2*t + b1; scatter into o
    gemm_kernel<0><<<gemm_blocks, 256, SMEM>>>(p_h, W1, b1, p_t, p_o, NN);
    edge_kernel<<<edge_blocks, 256>>>(srcp, dstp, p_t, p_o);

    // Layer 2: relu(o) -> t; h = dinv^2*t + b2; scatter into h
    gemm_kernel<1><<<gemm_blocks, 256, SMEM>>>(p_o, W2, b2, p_t, p_h, NN);
    edge_kernel<<<edge_blocks, 256>>>(srcp, dstp, p_t, p_h);

    // Layer 3: relu(h) -> t; o = dinv^2*t + b3; scatter into o
    gemm_kernel<1><<<gemm_blocks, 256, SMEM>>>(p_h, W3, b3, p_t, p_o, NN);
    edge_kernel<<<edge_blocks, 256>>>(srcp, dstp, p_t, p_o);

    // Mean pool + final linear
    pool_zero_kernel<<<(GG * HH + 255) / 256, 256>>>();
    pool_scatter_kernel<<<(NN * 32 + 255) / 256, 256>>>(batch, p_o);
    gemm_kernel<2><<<(GG + 127) / 128, 256, SMEM>>>(p_pool, Wl, bl, nullptr, out, GG);
}

// round 10
// speedup vs baseline: 1.0275x; 1.0275x over previous
#include <cuda_runtime.h>
#include <cuda_bf16.h>

// Problem constants (fixed shapes per reference)
#define NN 100000
#define EE 600000
#define HH 128
#define GG 4000
#define TT 128

// Scratch (allocation-free: device globals)
__device__ float g_deg[NN];                 // degree, then dinv in-place
__device__ float g_h[(size_t)NN * HH];
__device__ float g_t[(size_t)NN * HH];
__device__ float g_o[(size_t)NN * HH];
__device__ float g_pool[(size_t)GG * HH];
__device__ float g_cnt[GG];

__constant__ int c_off[9] = {0, 119, 124, 136, 148, 158, 164, 170, 172};

// ---------------------------------------------------------------------------
__global__ void deg_init_kernel() {
    int i = blockIdx.x * blockDim.x + threadIdx.x;
    if (i < NN) g_deg[i] = 1.0f;
}

__global__ void deg_scatter_kernel(const int* __restrict__ dst) {
    int e = blockIdx.x * blockDim.x + threadIdx.x;
    if (e < EE) atomicAdd(&g_deg[dst[e]], 1.0f);
}

// AtomEncoder: h[n] = sum_f emb[x[n,f]+off[f]]; also deg -> dinv in place.
__global__ void embed_kernel(const int* __restrict__ x, const float* __restrict__ emb) {
    int n = blockIdx.x;
    int t = threadIdx.x;
    __shared__ int xi[9];
    if (t < 9) xi[t] = x[n * 9 + t] + c_off[t];
    __syncthreads();
    float v = 0.0f;
#pragma unroll
    for (int f = 0; f < 9; f++) v += emb[(size_t)xi[f] * HH + t];
    g_h[(size_t)n * HH + t] = v;
    if (t == 0) g_deg[n] = rsqrtf(g_deg[n]);
}

// ---------------------------------------------------------------------------
// Persistent GEMM: C[M,128] = A'[M,128] @ B[128,128]
// MODE 0: layer, A as-is.  MODE 1: layer, relu(A) (fused in compute loop).
// MODE 2: final, row-scale 1/max(cnt,1) applied in EPILOGUE (gemm linear in A).
// Layer epilogue: T = A'@B ; OUT = dinv^2 * T + bias   (self-loop init)
// Final epilogue: OUT = scale * (A'@B) + bias
//
// B (64KB) resident per SM for the whole kernel; A tile double-buffered
// (2 x 64KB) and prefetched with cp.async while the current tile computes.
// Inner loop: packed fma.rn.f32x2 (bit-identical rounding to scalar FFMA).
template <int MODE>
__global__ void __launch_bounds__(256, 1)
gemm_kernel(const float* __restrict__ A, const float* __restrict__ B,
            const float* __restrict__ bias, float* __restrict__ T,
            float* __restrict__ OUT, int M, int numTiles) {
    extern __shared__ float sm[];
    float* Bs = sm;                          // [k][col], 128x128

    const int tid = threadIdx.x;             // 256 threads

    // Stage B once (whole 128x128), async.
#pragma unroll
    for (int i = tid; i < 4096; i += 256) {
        const int r = i >> 5, c = (i & 31) << 2;
        const unsigned int d = (unsigned int)__cvta_generic_to_shared(&Bs[r * 128 + c]);
        asm volatile("cp.async.cg.shared.global [%0], [%1], 16;"
                     :: "r"(d), "l"(B + r * 128 + c));
    }
    asm volatile("cp.async.commit_group;");

    const int tx = tid & 15;                  // 16 col groups
    const int ty = tid >> 4;                  // 16 row groups
    const int c0 = tx << 3;                   // 8 cols / thread
    const int r0t = ty << 3;                  // 8 rows / thread

    // bias fragment (constant across tiles)
    float bsv[8];
    {
        const float4 bl0 = *(const float4*)&bias[c0];
        const float4 bl1 = *(const float4*)&bias[c0 + 4];
        bsv[0] = bl0.x; bsv[1] = bl0.y; bsv[2] = bl0.z; bsv[3] = bl0.w;
        bsv[4] = bl1.x; bsv[5] = bl1.y; bsv[6] = bl1.z; bsv[7] = bl1.w;
    }

    // Stage first A tile into buffer 0.
    int tile = blockIdx.x;
    {
        const int row0 = tile * 128;
        float* dst = sm + 16384;              // buffer 0
#pragma unroll
        for (int i = tid; i < 4096; i += 256) {
            const int r = i >> 5, c = (i & 31) << 2;
            const int gr = row0 + r;
            const float* gp = (gr < M) ? (A + (size_t)gr * HH + c) : A;
            const int sz = (gr < M) ? 16 : 0;
            const unsigned int d = (unsigned int)__cvta_generic_to_shared(&dst[r * 128 + c]);
            asm volatile("cp.async.cg.shared.global [%0], [%1], 16, %2;"
                         :: "r"(d), "l"(gp), "r"(sz));
        }
        asm volatile("cp.async.commit_group;");
    }
    asm volatile("cp.async.wait_group 0;");
    __syncthreads();

    int buf = 0;
    for (; tile < numTiles; tile += gridDim.x) {
        const int next = tile + gridDim.x;
        // Prefetch next A tile into the other buffer (overlaps compute).
        if (next < numTiles) {
            const int row0n = next * 128;
            float* dst = sm + 16384 + ((buf ^ 1) << 14);
#pragma unroll
            for (int i = tid; i < 4096; i += 256) {
                const int r = i >> 5, c = (i & 31) << 2;
                const int gr = row0n + r;
                const float* gp = (gr < M) ? (A + (size_t)gr * HH + c) : A;
                const int sz = (gr < M) ? 16 : 0;
                const unsigned int d = (unsigned int)__cvta_generic_to_shared(&dst[r * 128 + c]);
                asm volatile("cp.async.cg.shared.global [%0], [%1], 16, %2;"
                             :: "r"(d), "l"(gp), "r"(sz));
            }
            asm volatile("cp.async.commit_group;");
        }

        // Compute current tile.
        const float* As = sm + 16384 + (buf << 14);
        unsigned long long acc[8][4];
#pragma unroll
        for (int i = 0; i < 8; i++)
#pragma unroll
            for (int j = 0; j < 4; j++) acc[i][j] = 0ull;

#pragma unroll 4
        for (int k = 0; k < 128; k++) {
            const ulonglong2 b01 = *(const ulonglong2*)&Bs[k * 128 + c0];
            const ulonglong2 b23 = *(const ulonglong2*)&Bs[k * 128 + c0 + 4];
            unsigned long long bb[4];
            bb[0] = b01.x; bb[1] = b01.y; bb[2] = b23.x; bb[3] = b23.y;
#pragma unroll
            for (int i = 0; i < 8; i++) {
                float a = As[(r0t + i) * 128 + k];     // 16-lane broadcast LDS
                if (MODE == 1) a = fmaxf(a, 0.f);
                unsigned long long a2;
                asm("mov.b64 %0, {%1, %1};" : "=l"(a2) : "f"(a));
#pragma unroll
                for (int j = 0; j < 4; j++)
                    asm("fma.rn.f32x2 %0, %1, %2, %0;" : "+l"(acc[i][j]) : "l"(a2), "l"(bb[j]));
            }
        }

        // Epilogue.
        const int row0 = tile * 128;
#pragma unroll
        for (int i = 0; i < 8; i++) {
            const int r = row0 + r0t + i;
            if (r >= M) continue;
            float v[8];
#pragma unroll
            for (int j = 0; j < 4; j++)
                asm("mov.b64 {%0, %1}, %2;" : "=f"(v[2 * j]), "=f"(v[2 * j + 1]) : "l"(acc[i][j]));
            if (MODE == 2) {
                const float s = 1.0f / fmaxf(g_cnt[r], 1.0f);
                float4 o0, o1;
                o0.x = fmaf(s, v[0], bsv[0]); o0.y = fmaf(s, v[1], bsv[1]);
                o0.z = fmaf(s, v[2], bsv[2]); o0.w = fmaf(s, v[3], bsv[3]);
                o1.x = fmaf(s, v[4], bsv[4]); o1.y = fmaf(s, v[5], bsv[5]);
                o1.z = fmaf(s, v[6], bsv[6]); o1.w = fmaf(s, v[7], bsv[7]);
                *(float4*)&OUT[(size_t)r * TT + c0] = o0;
                *(float4*)&OUT[(size_t)r * TT + c0 + 4] = o1;
            } else {
                const float d = g_deg[r];   // dinv
                const float d2 = d * d;
                float4 t0, t1, o0, o1;
                t0.x = v[0]; t0.y = v[1]; t0.z = v[2]; t0.w = v[3];
                t1.x = v[4]; t1.y = v[5]; t1.z = v[6]; t1.w = v[7];
                o0.x = fmaf(d2, v[0], bsv[0]); o0.y = fmaf(d2, v[1], bsv[1]);
                o0.z = fmaf(d2, v[2], bsv[2]); o0.w = fmaf(d2, v[3], bsv[3]);
                o1.x = fmaf(d2, v[4], bsv[4]); o1.y = fmaf(d2, v[5], bsv[5]);
                o1.z = fmaf(d2, v[6], bsv[6]); o1.w = fmaf(d2, v[7], bsv[7]);
                *(float4*)&T[(size_t)r * HH + c0] = t0;
                *(float4*)&T[(size_t)r * HH + c0 + 4] = t1;
                *(float4*)&OUT[(size_t)r * HH + c0] = o0;
                *(float4*)&OUT[(size_t)r * HH + c0 + 4] = o1;
            }
        }

        asm volatile("cp.async.wait_group 0;");
        __syncthreads();
        buf ^= 1;
    }
}

// ---------------------------------------------------------------------------
// Edge scatter: out[dst] += t[src] * dinv[src] * dinv[dst]   (one warp / edge)
__global__ void edge_kernel(const int* __restrict__ src, const int* __restrict__ dst,
                            const float* __restrict__ t, float* __restrict__ out) {
    const int w = (blockIdx.x * blockDim.x + threadIdx.x) >> 5;
    const int lane = threadIdx.x & 31;
    if (w >= EE) return;
    const int s = src[w];
    const int d = dst[w];
    const float c = g_deg[s] * g_deg[d];
    float4 v = *(const float4*)(t + (size_t)s * HH + (lane << 2));
    v.x *= c; v.y *= c; v.z *= c; v.w *= c;
    float* p = out + (size_t)d * HH + (lane << 2);
    asm volatile("red.global.add.v4.f32 [%0], {%1,%2,%3,%4};"
                 :: "l"(p), "f"(v.x), "f"(v.y), "f"(v.z), "f"(v.w)
                 : "memory");
}

// ---------------------------------------------------------------------------
__global__ void pool_zero_kernel() {
    int i = blockIdx.x * blockDim.x + threadIdx.x;
    if (i < GG * HH) g_pool[i] = 0.0f;
    if (i < GG) g_cnt[i] = 0.0f;
}

// one warp / node: pooled[batch[n]] += h[n]; cnt[batch[n]] += 1
__global__ void pool_scatter_kernel(const int* __restrict__ batch, const float* __restrict__ h) {
    const int n = (blockIdx.x * blockDim.x + threadIdx.x) >> 5;
    const int lane = threadIdx.x & 31;
    if (n >= NN) return;
    const int g = batch[n];
    float4 v = *(const float4*)(h + (size_t)n * HH + (lane << 2));
    float* p = g_pool + (size_t)g * HH + (lane << 2);
    asm volatile("red.global.add.v4.f32 [%0], {%1,%2,%3,%4};"
                 :: "l"(p), "f"(v.x), "f"(v.y), "f"(v.z), "f"(v.w)
                 : "memory");
    if (lane == 0) atomicAdd(&g_cnt[g], 1.0f);
}

// ---------------------------------------------------------------------------
extern "C" void kernel_launch(void* const* d_in, const int* in_sizes, int n_in,
                              void* d_out, int out_size) {
    const int*   x     = (const int*)d_in[0];
    const int*   ei    = (const int*)d_in[1];
    const int*   batch = (const int*)d_in[2];
    const float* emb   = (const float*)d_in[3];
    const float* W1    = (const float*)d_in[4];
    const float* b1    = (const float*)d_in[5];
    const float* W2    = (const float*)d_in[6];
    const float* b2    = (const float*)d_in[7];
    const float* W3    = (const float*)d_in[8];
    const float* b3    = (const float*)d_in[9];
    const float* Wl    = (const float*)d_in[10];
    const float* bl    = (const float*)d_in[11];
    float* out = (float*)d_out;

    const int* srcp = ei;
    const int* dstp = ei + EE;

    float *p_h, *p_t, *p_o, *p_pool;
    cudaGetSymbolAddress((void**)&p_h, g_h);
    cudaGetSymbolAddress((void**)&p_t, g_t);
    cudaGetSymbolAddress((void**)&p_o, g_o);
    cudaGetSymbolAddress((void**)&p_pool, g_pool);

    const int SMEM = 3 * 128 * 128 * (int)sizeof(float);   // 192KB: B + 2x A buffers
    static bool attr_set = false;
    if (!attr_set) {
        cudaFuncSetAttribute(gemm_kernel<0>, cudaFuncAttributeMaxDynamicSharedMemorySize, SMEM);
        cudaFuncSetAttribute(gemm_kernel<1>, cudaFuncAttributeMaxDynamicSharedMemorySize, SMEM);
        cudaFuncSetAttribute(gemm_kernel<2>, cudaFuncAttributeMaxDynamicSharedMemorySize, SMEM);
        attr_set = true;
    }

    // degree (with self-loop) -> dinv
    deg_init_kernel<<<(NN + 255) / 256, 256>>>();
    deg_scatter_kernel<<<(EE + 255) / 256, 256>>>(dstp);

    // atom embedding sum + dinv conversion
    embed_kernel<<<NN, 128>>>(x, emb);

    const int tilesN = (NN + 127) / 128;      // 782
    const int tilesG = (GG + 127) / 128;      // 32
    const int gridN = tilesN < 148 ? tilesN : 148;
    const int gridG = tilesG < 148 ? tilesG : 148;
    const int edge_blocks = (EE * 32 + 255) / 256;

    // Layer 1: h -> t; o = dinv^2*t + b1; scatter into o
    gemm_kernel<0><<<gridN, 256, SMEM>>>(p_h, W1, b1, p_t, p_o, NN, tilesN);
    edge_kernel<<<edge_blocks, 256>>>(srcp, dstp, p_t, p_o);

    // Layer 2: relu(o) -> t; h = dinv^2*t + b2; scatter into h
    gemm_kernel<1><<<gridN, 256, SMEM>>>(p_o, W2, b2, p_t, p_h, NN, tilesN);
    edge_kernel<<<edge_blocks, 256>>>(srcp, dstp, p_t, p_h);

    // Layer 3: relu(h) -> t; o = dinv^2*t + b3; scatter into o
    gemm_kernel<1><<<gridN, 256, SMEM>>>(p_h, W3, b3, p_t, p_o, NN, tilesN);
    edge_kernel<<<edge_blocks, 256>>>(srcp, dstp, p_t, p_o);

    // Mean pool + final linear
    pool_zero_kernel<<<(GG * HH + 255) / 256, 256>>>();
    pool_scatter_kernel<<<(NN * 32 + 255) / 256, 256>>>(batch, p_o);
    gemm_kernel<2><<<gridG, 256, SMEM>>>(p_pool, Wl, bl, nullptr, out, GG, tilesG);
}

// round 11
// speedup vs baseline: 1.0547x; 1.0264x over previous
#include <cuda_runtime.h>
#include <cuda_bf16.h>

// Problem constants (fixed shapes per reference)
#define NN 100000
#define EE 600000
#define HH 128
#define GG 4000
#define TT 128

// Scratch (allocation-free: device globals)
__device__ float g_deg[NN];                 // degree, then dinv in-place
__device__ float g_h[(size_t)NN * HH];
__device__ float g_t[(size_t)NN * HH];
__device__ float g_o[(size_t)NN * HH];
__device__ float g_pool[(size_t)GG * HH];
__device__ float g_cnt[GG];

__constant__ int c_off[9] = {0, 119, 124, 136, 148, 158, 164, 170, 172};

// ---------------------------------------------------------------------------
__global__ void deg_init_kernel() {
    int i = blockIdx.x * blockDim.x + threadIdx.x;
    if (i < NN) g_deg[i] = 1.0f;
}

__global__ void deg_scatter_kernel(const int* __restrict__ dst) {
    int e = blockIdx.x * blockDim.x + threadIdx.x;
    if (e < EE) atomicAdd(&g_deg[dst[e]], 1.0f);
}

// AtomEncoder: h[n] = sum_f emb[x[n,f]+off[f]]; also deg -> dinv in place.
__global__ void embed_kernel(const int* __restrict__ x, const float* __restrict__ emb) {
    int n = blockIdx.x;
    int t = threadIdx.x;
    __shared__ int xi[9];
    if (t < 9) xi[t] = x[n * 9 + t] + c_off[t];
    __syncthreads();
    float v = 0.0f;
#pragma unroll
    for (int f = 0; f < 9; f++) v += emb[(size_t)xi[f] * HH + t];
    g_h[(size_t)n * HH + t] = v;
    if (t == 0) g_deg[n] = rsqrtf(g_deg[n]);
}

// ---------------------------------------------------------------------------
// Persistent GEMM: C[M,128] = A'[M,128] @ B[128,128]
// K-PAIR PACKED f32x2: acc{lo,hi} = partial sums over even/odd k.
//   x = {A[r][2k],A[r][2k+1]}  -> natural LDS.64 from row-major A (no MOV)
//   y = {B[2k][c],B[2k+1][c]}  -> LDS.128 from k-pair-interleaved Bp (built once)
// Thread (tx,ty) owns rows ty*8..+7, cols {32q + 2*tx, 32q + 2*tx + 1 : q=0..3}
// (16B lane stride -> conflict-free y loads; float2 epilogue stores).
// MODE 0: layer, A as-is.  MODE 1: layer, relu(A) via in-smem pass.
// MODE 2: final, row-scale 1/max(cnt,1) in epilogue.
// Layer epilogue: T = A'@B ; OUT = dinv^2 * T + bias.
template <int MODE>
__global__ void __launch_bounds__(256, 1)
gemm_kernel(const float* __restrict__ A, const float* __restrict__ B,
            const float* __restrict__ bias, float* __restrict__ T,
            float* __restrict__ OUT, int M, int numTiles) {
    extern __shared__ float sm[];
    // Bp: 64 k-pairs x 128 cols of float2 = 16384 floats at [0, 16384)
    // A buffers: 128x128 floats each at [16384, 32768) and [32768, 49152)
    const int tid = threadIdx.x;              // 256 threads
    const int tx = tid & 15;                  // 16 col groups
    const int ty = tid >> 4;                  // 16 row groups
    const int r0t = ty << 3;                  // 8 rows / thread

    // Stage first A tile into buffer 0 (async).
    int tile = blockIdx.x;
    {
        const int row0 = tile * 128;
        float* dst = sm + 16384;
#pragma unroll
        for (int i = tid; i < 4096; i += 256) {
            const int r = i >> 5, c = (i & 31) << 2;
            const int gr = row0 + r;
            const float* gp = (gr < M) ? (A + (size_t)gr * HH + c) : A;
            const int sz = (gr < M) ? 16 : 0;
            const unsigned int d = (unsigned int)__cvta_generic_to_shared(&dst[r * 128 + c]);
            asm volatile("cp.async.cg.shared.global [%0], [%1], 16, %2;"
                         :: "r"(d), "l"(gp), "r"(sz));
        }
        asm volatile("cp.async.commit_group;");
    }

    // Build Bp (k-pair interleave of B), overlapping the A load.
    {
        float2* Bp = (float2*)sm;
#pragma unroll
        for (int i = tid; i < 8192; i += 256) {
            const int kk = i >> 7, c = i & 127;
            Bp[i] = make_float2(B[(2 * kk) * 128 + c], B[(2 * kk + 1) * 128 + c]);
        }
    }

    // bias fragment at cols 32q + 2tx (+1)
    float bsv[8];
#pragma unroll
    for (int q = 0; q < 4; q++) {
        const float2 b2 = *(const float2*)&bias[32 * q + 2 * tx];
        bsv[2 * q] = b2.x; bsv[2 * q + 1] = b2.y;
    }

    asm volatile("cp.async.wait_group 0;");
    __syncthreads();

    if (MODE == 1) {   // relu first tile in smem
        float4* p = (float4*)(sm + 16384);
#pragma unroll
        for (int i = tid; i < 4096; i += 256) {
            float4 v = p[i];
            v.x = fmaxf(v.x, 0.f); v.y = fmaxf(v.y, 0.f);
            v.z = fmaxf(v.z, 0.f); v.w = fmaxf(v.w, 0.f);
            p[i] = v;
        }
        __syncthreads();
    }

    int buf = 0;
    const unsigned long long* BpU = (const unsigned long long*)sm;

    for (; tile < numTiles; tile += gridDim.x) {
        const int next = tile + gridDim.x;
        // Prefetch next A tile into the other buffer (overlaps compute).
        if (next < numTiles) {
            const int row0n = next * 128;
            float* dst = sm + 16384 + ((buf ^ 1) << 14);
#pragma unroll
            for (int i = tid; i < 4096; i += 256) {
                const int r = i >> 5, c = (i & 31) << 2;
                const int gr = row0n + r;
                const float* gp = (gr < M) ? (A + (size_t)gr * HH + c) : A;
                const int sz = (gr < M) ? 16 : 0;
                const unsigned int d = (unsigned int)__cvta_generic_to_shared(&dst[r * 128 + c]);
                asm volatile("cp.async.cg.shared.global [%0], [%1], 16, %2;"
                             :: "r"(d), "l"(gp), "r"(sz));
            }
            asm volatile("cp.async.commit_group;");
        }

        // ---- Compute current tile ----
        const float* As = sm + 16384 + (buf << 14);
        unsigned long long acc[8][8];
#pragma unroll
        for (int i = 0; i < 8; i++)
#pragma unroll
            for (int j = 0; j < 8; j++) acc[i][j] = 0ull;

#pragma unroll 2
        for (int kk = 0; kk < 64; kk++) {
            unsigned long long y[8];
            {
                const unsigned long long* yb = BpU + kk * 128 + 2 * tx;
                const ulonglong2 t0 = *(const ulonglong2*)(yb);
                const ulonglong2 t1 = *(const ulonglong2*)(yb + 32);
                const ulonglong2 t2 = *(const ulonglong2*)(yb + 64);
                const ulonglong2 t3 = *(const ulonglong2*)(yb + 96);
                y[0] = t0.x; y[1] = t0.y; y[2] = t1.x; y[3] = t1.y;
                y[4] = t2.x; y[5] = t2.y; y[6] = t3.x; y[7] = t3.y;
            }
#pragma unroll
            for (int i = 0; i < 8; i++) {
                const unsigned long long x =
                    *(const unsigned long long*)(As + (r0t + i) * 128 + 2 * kk);
#pragma unroll
                for (int j = 0; j < 8; j++)
                    asm("fma.rn.f32x2 %0, %1, %2, %0;" : "+l"(acc[i][j]) : "l"(x), "l"(y[j]));
            }
        }

        // Next tile's data lands while we run the epilogue; wait first so we
        // can also relu it in smem before the buffer flip.
        asm volatile("cp.async.wait_group 0;");
        __syncthreads();
        if (MODE == 1 && next < numTiles) {
            float4* p = (float4*)(sm + 16384 + ((buf ^ 1) << 14));
#pragma unroll
            for (int i = tid; i < 4096; i += 256) {
                float4 v = p[i];
                v.x = fmaxf(v.x, 0.f); v.y = fmaxf(v.y, 0.f);
                v.z = fmaxf(v.z, 0.f); v.w = fmaxf(v.w, 0.f);
                p[i] = v;
            }
        }

        // ---- Epilogue ----
        const int row0 = tile * 128;
#pragma unroll
        for (int i = 0; i < 8; i++) {
            const int r = row0 + r0t + i;
            if (r >= M) continue;
            float vv[8];
#pragma unroll
            for (int j = 0; j < 8; j++) {
                float lo, hi;
                asm("mov.b64 {%0, %1}, %2;" : "=f"(lo), "=f"(hi) : "l"(acc[i][j]));
                vv[j] = lo + hi;
            }
            if (MODE == 2) {
                const float s = 1.0f / fmaxf(g_cnt[r], 1.0f);
#pragma unroll
                for (int q = 0; q < 4; q++) {
                    float2 o;
                    o.x = fmaf(s, vv[2 * q], bsv[2 * q]);
                    o.y = fmaf(s, vv[2 * q + 1], bsv[2 * q + 1]);
                    *(float2*)&OUT[(size_t)r * TT + 32 * q + 2 * tx] = o;
                }
            } else {
                const float d = g_deg[r];   // dinv
                const float d2 = d * d;
#pragma unroll
                for (int q = 0; q < 4; q++) {
                    const int c = 32 * q + 2 * tx;
                    float2 t2, o2;
                    t2.x = vv[2 * q];     t2.y = vv[2 * q + 1];
                    o2.x = fmaf(d2, vv[2 * q], bsv[2 * q]);
                    o2.y = fmaf(d2, vv[2 * q + 1], bsv[2 * q + 1]);
                    *(float2*)&T[(size_t)r * HH + c] = t2;
                    *(float2*)&OUT[(size_t)r * HH + c] = o2;
                }
            }
        }

        __syncthreads();   // relu visibility + safe to overwrite old buffer
        buf ^= 1;
    }
}

// ---------------------------------------------------------------------------
// Edge scatter: out[dst] += t[src] * dinv[src] * dinv[dst]   (one warp / edge)
__global__ void edge_kernel(const int* __restrict__ src, const int* __restrict__ dst,
                            const float* __restrict__ t, float* __restrict__ out) {
    const int w = (blockIdx.x * blockDim.x + threadIdx.x) >> 5;
    const int lane = threadIdx.x & 31;
    if (w >= EE) return;
    const int s = src[w];
    const int d = dst[w];
    const float c = g_deg[s] * g_deg[d];
    float4 v = *(const float4*)(t + (size_t)s * HH + (lane << 2));
    v.x *= c; v.y *= c; v.z *= c; v.w *= c;
    float* p = out + (size_t)d * HH + (lane << 2);
    asm volatile("red.global.add.v4.f32 [%0], {%1,%2,%3,%4};"
                 :: "l"(p), "f"(v.x), "f"(v.y), "f"(v.z), "f"(v.w)
                 : "memory");
}

// ---------------------------------------------------------------------------
__global__ void pool_zero_kernel() {
    int i = blockIdx.x * blockDim.x + threadIdx.x;
    if (i < GG * HH) g_pool[i] = 0.0f;
    if (i < GG) g_cnt[i] = 0.0f;
}

// one warp / node: pooled[batch[n]] += h[n]; cnt[batch[n]] += 1
__global__ void pool_scatter_kernel(const int* __restrict__ batch, const float* __restrict__ h) {
    const int n = (blockIdx.x * blockDim.x + threadIdx.x) >> 5;
    const int lane = threadIdx.x & 31;
    if (n >= NN) return;
    const int g = batch[n];
    float4 v = *(const float4*)(h + (size_t)n * HH + (lane << 2));
    float* p = g_pool + (size_t)g * HH + (lane << 2);
    asm volatile("red.global.add.v4.f32 [%0], {%1,%2,%3,%4};"
                 :: "l"(p), "f"(v.x), "f"(v.y), "f"(v.z), "f"(v.w)
                 : "memory");
    if (lane == 0) atomicAdd(&g_cnt[g], 1.0f);
}

// ---------------------------------------------------------------------------
extern "C" void kernel_launch(void* const* d_in, const int* in_sizes, int n_in,
                              void* d_out, int out_size) {
    const int*   x     = (const int*)d_in[0];
    const int*   ei    = (const int*)d_in[1];
    const int*   batch = (const int*)d_in[2];
    const float* emb   = (const float*)d_in[3];
    const float* W1    = (const float*)d_in[4];
    const float* b1    = (const float*)d_in[5];
    const float* W2    = (const float*)d_in[6];
    const float* b2    = (const float*)d_in[7];
    const float* W3    = (const float*)d_in[8];
    const float* b3    = (const float*)d_in[9];
    const float* Wl    = (const float*)d_in[10];
    const float* bl    = (const float*)d_in[11];
    float* out = (float*)d_out;

    const int* srcp = ei;
    const int* dstp = ei + EE;

    float *p_h, *p_t, *p_o, *p_pool;
    cudaGetSymbolAddress((void**)&p_h, g_h);
    cudaGetSymbolAddress((void**)&p_t, g_t);
    cudaGetSymbolAddress((void**)&p_o, g_o);
    cudaGetSymbolAddress((void**)&p_pool, g_pool);

    const int SMEM = 3 * 128 * 128 * (int)sizeof(float);   // 192KB: Bp + 2x A buffers
    static bool attr_set = false;
    if (!attr_set) {
        cudaFuncSetAttribute(gemm_kernel<0>, cudaFuncAttributeMaxDynamicSharedMemorySize, SMEM);
        cudaFuncSetAttribute(gemm_kernel<1>, cudaFuncAttributeMaxDynamicSharedMemorySize, SMEM);
        cudaFuncSetAttribute(gemm_kernel<2>, cudaFuncAttributeMaxDynamicSharedMemorySize, SMEM);
        attr_set = true;
    }

    // degree (with self-loop) -> dinv
    deg_init_kernel<<<(NN + 255) / 256, 256>>>();
    deg_scatter_kernel<<<(EE + 255) / 256, 256>>>(dstp);

    // atom embedding sum + dinv conversion
    embed_kernel<<<NN, 128>>>(x, emb);

    const int tilesN = (NN + 127) / 128;      // 782
    const int tilesG = (GG + 127) / 128;      // 32
    const int gridN = tilesN < 148 ? tilesN : 148;
    const int gridG = tilesG < 148 ? tilesG : 148;
    const int edge_blocks = (EE * 32 + 255) / 256;

    // Layer 1: h -> t; o = dinv^2*t + b1; scatter into o
    gemm_kernel<0><<<gridN, 256, SMEM>>>(p_h, W1, b1, p_t, p_o, NN, tilesN);
    edge_kernel<<<edge_blocks, 256>>>(srcp, dstp, p_t, p_o);

    // Layer 2: relu(o) -> t; h = dinv^2*t + b2; scatter into h
    gemm_kernel<1><<<gridN, 256, SMEM>>>(p_o, W2, b2, p_t, p_h, NN, tilesN);
    edge_kernel<<<edge_blocks, 256>>>(srcp, dstp, p_t, p_h);

    // Layer 3: relu(h) -> t; o = dinv^2*t + b3; scatter into o
    gemm_kernel<1><<<gridN, 256, SMEM>>>(p_h, W3, b3, p_t, p_o, NN, tilesN);
    edge_kernel<<<edge_blocks, 256>>>(srcp, dstp, p_t, p_o);

    // Mean pool + final linear
    pool_zero_kernel<<<(GG * HH + 255) / 256, 256>>>();
    pool_scatter_kernel<<<(NN * 32 + 255) / 256, 256>>>(batch, p_o);
    gemm_kernel<2><<<gridG, 256, SMEM>>>(p_pool, Wl, bl, nullptr, out, GG, tilesG);
}

// round 12
// speedup vs baseline: 1.4116x; 1.3383x over previous
#include <cuda_runtime.h>
#include <cuda_bf16.h>

// Problem constants (fixed shapes per reference)
#define NN 100000
#define EE 600000
#define HH 128
#define GG 4000
#define TT 128

#define SCAN_B 512
#define NB ((NN + SCAN_B - 1) / SCAN_B)   // 196 scan blocks

// Scratch (allocation-free: device globals)
__device__ float g_deg[NN];                 // dinv
__device__ float g_h[(size_t)NN * HH];
__device__ float g_t[(size_t)NN * HH];      // T' = dinv * (A@B)
__device__ float g_o[(size_t)NN * HH];
__device__ float g_pool[(size_t)GG * HH];
__device__ float g_cnt[GG];
__device__ int   g_cnti[NN];                // in-degree counts
__device__ int   g_cur[NN];                 // fill cursors
__device__ int   g_rs[NN + 1];              // CSR row starts
__device__ int   g_csr[EE];                 // CSR src indices
__device__ int   g_bsum[NB];                // per-block sums for scan

__constant__ int c_off[9] = {0, 119, 124, 136, 148, 158, 164, 170, 172};

// ---------------------------------------------------------------------------
// CSR build
__global__ void count_zero_kernel() {
    int i = blockIdx.x * blockDim.x + threadIdx.x;
    if (i < NN) { g_cnti[i] = 0; g_cur[i] = 0; }
}

__global__ void count_kernel(const int* __restrict__ dst) {
    int e = blockIdx.x * blockDim.x + threadIdx.x;
    if (e < EE) atomicAdd(&g_cnti[dst[e]], 1);
}

__global__ void blocksum_kernel() {        // NB blocks x SCAN_B threads
    __shared__ int s[SCAN_B];
    const int n = blockIdx.x * SCAN_B + threadIdx.x;
    s[threadIdx.x] = (n < NN) ? g_cnti[n] : 0;
    __syncthreads();
    for (int off = SCAN_B / 2; off > 0; off >>= 1) {
        if (threadIdx.x < off) s[threadIdx.x] += s[threadIdx.x + off];
        __syncthreads();
    }
    if (threadIdx.x == 0) g_bsum[blockIdx.x] = s[0];
}

__global__ void scanblock_kernel() {       // 1 block x 256 threads, NB<=256
    __shared__ int s[256];
    const int t = threadIdx.x;
    const int v = (t < NB) ? g_bsum[t] : 0;
    s[t] = v;
    __syncthreads();
    for (int off = 1; off < 256; off <<= 1) {
        int u = (t >= off) ? s[t - off] : 0;
        __syncthreads();
        s[t] += u;
        __syncthreads();
    }
    if (t < NB) g_bsum[t] = s[t] - v;       // exclusive
}

__global__ void rowstart_kernel() {        // NB blocks x SCAN_B threads
    __shared__ int s[SCAN_B];
    const int t = threadIdx.x;
    const int n = blockIdx.x * SCAN_B + t;
    const int v = (n < NN) ? g_cnti[n] : 0;
    s[t] = v;
    __syncthreads();
    for (int off = 1; off < SCAN_B; off <<= 1) {
        int u = (t >= off) ? s[t - off] : 0;
        __syncthreads();
        s[t] += u;
        __syncthreads();
    }
    if (n < NN) {
        g_rs[n] = s[t] - v + g_bsum[blockIdx.x];           // exclusive prefix
        g_deg[n] = rsqrtf((float)v + 1.0f);                // dinv (self-loop)
    }
    if (blockIdx.x == 0 && t == 0) g_rs[NN] = EE;
}

__global__ void fill_kernel(const int* __restrict__ src, const int* __restrict__ dst) {
    int e = blockIdx.x * blockDim.x + threadIdx.x;
    if (e >= EE) return;
    const int d = dst[e];
    const int pos = g_rs[d] + atomicAdd(&g_cur[d], 1);
    g_csr[pos] = src[e];
}

// ---------------------------------------------------------------------------
// AtomEncoder: h[n] = sum_f emb[x[n,f]+off[f]]
__global__ void embed_kernel(const int* __restrict__ x, const float* __restrict__ emb) {
    int n = blockIdx.x;
    int t = threadIdx.x;
    __shared__ int xi[9];
    if (t < 9) xi[t] = x[n * 9 + t] + c_off[t];
    __syncthreads();
    float v = 0.0f;
#pragma unroll
    for (int f = 0; f < 9; f++) v += emb[(size_t)xi[f] * HH + t];
    g_h[(size_t)n * HH + t] = v;
}

// ---------------------------------------------------------------------------
// Persistent GEMM: K-pair packed f32x2 (see R11 comments).
// MODE 0: layer. Epilogue stores ONLY T'[r] = dinv[r] * (A@B)[r].
// MODE 2: final. Epilogue: OUT = (A@B)/max(cnt,1) + bias.
template <int MODE>
__global__ void __launch_bounds__(256, 1)
gemm_kernel(const float* __restrict__ A, const float* __restrict__ B,
            const float* __restrict__ bias, float* __restrict__ T,
            float* __restrict__ OUT, int M, int numTiles) {
    extern __shared__ float sm[];
    const int tid = threadIdx.x;              // 256 threads
    const int tx = tid & 15;                  // 16 col groups
    const int ty = tid >> 4;                  // 16 row groups
    const int r0t = ty << 3;                  // 8 rows / thread

    // Stage first A tile into buffer 0 (async).
    int tile = blockIdx.x;
    {
        const int row0 = tile * 128;
        float* dst = sm + 16384;
#pragma unroll
        for (int i = tid; i < 4096; i += 256) {
            const int r = i >> 5, c = (i & 31) << 2;
            const int gr = row0 + r;
            const float* gp = (gr < M) ? (A + (size_t)gr * HH + c) : A;
            const int sz = (gr < M) ? 16 : 0;
            const unsigned int d = (unsigned int)__cvta_generic_to_shared(&dst[r * 128 + c]);
            asm volatile("cp.async.cg.shared.global [%0], [%1], 16, %2;"
                         :: "r"(d), "l"(gp), "r"(sz));
        }
        asm volatile("cp.async.commit_group;");
    }

    // Build Bp (k-pair interleave of B), overlapping the A load.
    {
        float2* Bp = (float2*)sm;
#pragma unroll
        for (int i = tid; i < 8192; i += 256) {
            const int kk = i >> 7, c = i & 127;
            Bp[i] = make_float2(B[(2 * kk) * 128 + c], B[(2 * kk + 1) * 128 + c]);
        }
    }

    float bsv[8];
    if (MODE == 2) {
#pragma unroll
        for (int q = 0; q < 4; q++) {
            const float2 b2 = *(const float2*)&bias[32 * q + 2 * tx];
            bsv[2 * q] = b2.x; bsv[2 * q + 1] = b2.y;
        }
    }

    asm volatile("cp.async.wait_group 0;");
    __syncthreads();

    int buf = 0;
    const unsigned long long* BpU = (const unsigned long long*)sm;

    for (; tile < numTiles; tile += gridDim.x) {
        const int next = tile + gridDim.x;
        if (next < numTiles) {
            const int row0n = next * 128;
            float* dst = sm + 16384 + ((buf ^ 1) << 14);
#pragma unroll
            for (int i = tid; i < 4096; i += 256) {
                const int r = i >> 5, c = (i & 31) << 2;
                const int gr = row0n + r;
                const float* gp = (gr < M) ? (A + (size_t)gr * HH + c) : A;
                const int sz = (gr < M) ? 16 : 0;
                const unsigned int d = (unsigned int)__cvta_generic_to_shared(&dst[r * 128 + c]);
                asm volatile("cp.async.cg.shared.global [%0], [%1], 16, %2;"
                             :: "r"(d), "l"(gp), "r"(sz));
            }
            asm volatile("cp.async.commit_group;");
        }

        const float* As = sm + 16384 + (buf << 14);
        unsigned long long acc[8][8];
#pragma unroll
        for (int i = 0; i < 8; i++)
#pragma unroll
            for (int j = 0; j < 8; j++) acc[i][j] = 0ull;

#pragma unroll 2
        for (int kk = 0; kk < 64; kk++) {
            unsigned long long y[8];
            {
                const unsigned long long* yb = BpU + kk * 128 + 2 * tx;
                const ulonglong2 t0 = *(const ulonglong2*)(yb);
                const ulonglong2 t1 = *(const ulonglong2*)(yb + 32);
                const ulonglong2 t2 = *(const ulonglong2*)(yb + 64);
                const ulonglong2 t3 = *(const ulonglong2*)(yb + 96);
                y[0] = t0.x; y[1] = t0.y; y[2] = t1.x; y[3] = t1.y;
                y[4] = t2.x; y[5] = t2.y; y[6] = t3.x; y[7] = t3.y;
            }
#pragma unroll
            for (int i = 0; i < 8; i++) {
                const unsigned long long x =
                    *(const unsigned long long*)(As + (r0t + i) * 128 + 2 * kk);
#pragma unroll
                for (int j = 0; j < 8; j++)
                    asm("fma.rn.f32x2 %0, %1, %2, %0;" : "+l"(acc[i][j]) : "l"(x), "l"(y[j]));
            }
        }

        const int row0 = tile * 128;
#pragma unroll
        for (int i = 0; i < 8; i++) {
            const int r = row0 + r0t + i;
            if (r >= M) continue;
            float vv[8];
#pragma unroll
            for (int j = 0; j < 8; j++) {
                float lo, hi;
                asm("mov.b64 {%0, %1}, %2;" : "=f"(lo), "=f"(hi) : "l"(acc[i][j]));
                vv[j] = lo + hi;
            }
            if (MODE == 2) {
                const float s = 1.0f / fmaxf(g_cnt[r], 1.0f);
#pragma unroll
                for (int q = 0; q < 4; q++) {
                    float2 o;
                    o.x = fmaf(s, vv[2 * q], bsv[2 * q]);
                    o.y = fmaf(s, vv[2 * q + 1], bsv[2 * q + 1]);
                    *(float2*)&OUT[(size_t)r * TT + 32 * q + 2 * tx] = o;
                }
            } else {
                const float d = g_deg[r];   // dinv
#pragma unroll
                for (int q = 0; q < 4; q++) {
                    float2 t2;
                    t2.x = d * vv[2 * q];
                    t2.y = d * vv[2 * q + 1];
                    *(float2*)&T[(size_t)r * HH + 32 * q + 2 * tx] = t2;
                }
            }
        }

        asm volatile("cp.async.wait_group 0;");
        __syncthreads();
        buf ^= 1;
    }
}

// ---------------------------------------------------------------------------
// Aggregator: one warp / node.  OUT[n] = dinv_n * (sum_{s->n} T'[s] + T'[n]) + bias
// RELU: apply relu on write (layers 1,2 feed relu'd input to the next GEMM).
template <bool RELU>
__global__ void agg_kernel(const float* __restrict__ Tp, const float* __restrict__ bias,
                           float* __restrict__ OUT) {
    const int n = (blockIdx.x * blockDim.x + threadIdx.x) >> 5;
    const int lane = threadIdx.x & 31;
    if (n >= NN) return;
    const int c = lane << 2;

    float4 acc = *(const float4*)(Tp + (size_t)n * HH + c);   // self term
    int i = g_rs[n];
    const int end = g_rs[n + 1];
    for (; i + 1 < end; i += 2) {
        const int s0 = g_csr[i];
        const int s1 = g_csr[i + 1];
        const float4 v0 = *(const float4*)(Tp + (size_t)s0 * HH + c);
        const float4 v1 = *(const float4*)(Tp + (size_t)s1 * HH + c);
        acc.x += v0.x; acc.y += v0.y; acc.z += v0.z; acc.w += v0.w;
        acc.x += v1.x; acc.y += v1.y; acc.z += v1.z; acc.w += v1.w;
    }
    if (i < end) {
        const int s0 = g_csr[i];
        const float4 v0 = *(const float4*)(Tp + (size_t)s0 * HH + c);
        acc.x += v0.x; acc.y += v0.y; acc.z += v0.z; acc.w += v0.w;
    }

    const float d = g_deg[n];
    const float4 b = *(const float4*)(bias + c);
    float4 o;
    o.x = fmaf(d, acc.x, b.x);
    o.y = fmaf(d, acc.y, b.y);
    o.z = fmaf(d, acc.z, b.z);
    o.w = fmaf(d, acc.w, b.w);
    if (RELU) {
        o.x = fmaxf(o.x, 0.f); o.y = fmaxf(o.y, 0.f);
        o.z = fmaxf(o.z, 0.f); o.w = fmaxf(o.w, 0.f);
    }
    *(float4*)(OUT + (size_t)n * HH + c) = o;
}

// ---------------------------------------------------------------------------
__global__ void pool_zero_kernel() {
    int i = blockIdx.x * blockDim.x + threadIdx.x;
    if (i < GG * HH) g_pool[i] = 0.0f;
    if (i < GG) g_cnt[i] = 0.0f;
}

// one warp / node: pooled[batch[n]] += h[n]; cnt[batch[n]] += 1
__global__ void pool_scatter_kernel(const int* __restrict__ batch, const float* __restrict__ h) {
    const int n = (blockIdx.x * blockDim.x + threadIdx.x) >> 5;
    const int lane = threadIdx.x & 31;
    if (n >= NN) return;
    const int g = batch[n];
    float4 v = *(const float4*)(h + (size_t)n * HH + (lane << 2));
    float* p = g_pool + (size_t)g * HH + (lane << 2);
    asm volatile("red.global.add.v4.f32 [%0], {%1,%2,%3,%4};"
                 :: "l"(p), "f"(v.x), "f"(v.y), "f"(v.z), "f"(v.w)
                 : "memory");
    if (lane == 0) atomicAdd(&g_cnt[g], 1.0f);
}

// ---------------------------------------------------------------------------
extern "C" void kernel_launch(void* const* d_in, const int* in_sizes, int n_in,
                              void* d_out, int out_size) {
    const int*   x     = (const int*)d_in[0];
    const int*   ei    = (const int*)d_in[1];
    const int*   batch = (const int*)d_in[2];
    const float* emb   = (const float*)d_in[3];
    const float* W1    = (const float*)d_in[4];
    const float* b1    = (const float*)d_in[5];
    const float* W2    = (const float*)d_in[6];
    const float* b2    = (const float*)d_in[7];
    const float* W3    = (const float*)d_in[8];
    const float* b3    = (const float*)d_in[9];
    const float* Wl    = (const float*)d_in[10];
    const float* bl    = (const float*)d_in[11];
    float* out = (float*)d_out;

    const int* srcp = ei;
    const int* dstp = ei + EE;

    float *p_h, *p_t, *p_o, *p_pool;
    cudaGetSymbolAddress((void**)&p_h, g_h);
    cudaGetSymbolAddress((void**)&p_t, g_t);
    cudaGetSymbolAddress((void**)&p_o, g_o);
    cudaGetSymbolAddress((void**)&p_pool, g_pool);

    const int SMEM = 3 * 128 * 128 * (int)sizeof(float);   // 192KB: Bp + 2x A buffers
    static bool attr_set = false;
    if (!attr_set) {
        cudaFuncSetAttribute(gemm_kernel<0>, cudaFuncAttributeMaxDynamicSharedMemorySize, SMEM);
        cudaFuncSetAttribute(gemm_kernel<2>, cudaFuncAttributeMaxDynamicSharedMemorySize, SMEM);
        attr_set = true;
    }

    // ---- CSR build (also computes dinv) ----
    count_zero_kernel<<<(NN + 255) / 256, 256>>>();
    count_kernel<<<(EE + 255) / 256, 256>>>(dstp);
    blocksum_kernel<<<NB, SCAN_B>>>();
    scanblock_kernel<<<1, 256>>>();
    rowstart_kernel<<<NB, SCAN_B>>>();
    fill_kernel<<<(EE + 255) / 256, 256>>>(srcp, dstp);

    // atom embedding sum
    embed_kernel<<<NN, 128>>>(x, emb);

    const int tilesN = (NN + 127) / 128;      // 782
    const int tilesG = (GG + 127) / 128;      // 32
    const int gridN = tilesN < 148 ? tilesN : 148;
    const int gridG = tilesG < 148 ? tilesG : 148;
    const int agg_blocks = (NN * 32 + 255) / 256;

    // Layer 1: t' = dinv*(h@W1); o = relu(agg(t') + b1)
    gemm_kernel<0><<<gridN, 256, SMEM>>>(p_h, W1, nullptr, p_t, nullptr, NN, tilesN);
    agg_kernel<true><<<agg_blocks, 256>>>(p_t, b1, p_o);

    // Layer 2: t' = dinv*(o@W2); h = relu(agg(t') + b2)
    gemm_kernel<0><<<gridN, 256, SMEM>>>(p_o, W2, nullptr, p_t, nullptr, NN, tilesN);
    agg_kernel<true><<<agg_blocks, 256>>>(p_t, b2, p_h);

    // Layer 3: t' = dinv*(h@W3); o = agg(t') + b3   (no relu)
    gemm_kernel<0><<<gridN, 256, SMEM>>>(p_h, W3, nullptr, p_t, nullptr, NN, tilesN);
    agg_kernel<false><<<agg_blocks, 256>>>(p_t, b3, p_o);

    // Mean pool + final linear
    pool_zero_kernel<<<(GG * HH + 255) / 256, 256>>>();
    pool_scatter_kernel<<<(NN * 32 + 255) / 256, 256>>>(batch, p_o);
    gemm_kernel<2><<<gridG, 256, SMEM>>>(p_pool, Wl, bl, nullptr, out, GG, tilesG);
}

// round 13
// speedup vs baseline: 1.4188x; 1.0051x over previous
#include <cuda_runtime.h>
#include <cuda_bf16.h>

// Problem constants (fixed shapes per reference)
#define NN 100000
#define EE 600000
#define HH 128
#define GG 4000
#define TT 128

#define SCAN_B 512
#define NB ((NN + SCAN_B - 1) / SCAN_B)   // 196 scan blocks

// Scratch (allocation-free: device globals)
__device__ float g_deg[NN];                 // dinv
__device__ float g_h[(size_t)NN * HH];
__device__ float g_t[(size_t)NN * HH];      // T' = dinv * (A@B)
__device__ float g_o[(size_t)NN * HH];
__device__ float g_pool[(size_t)GG * HH];
__device__ float g_cnt[GG];
__device__ int   g_cnti[NN];                // in-degree counts
__device__ int   g_cur[NN];                 // fill cursors
__device__ int   g_rs[NN + 1];              // CSR row starts
__device__ int   g_csr[EE];                 // CSR src indices
__device__ int   g_bsum[NB];                // per-block sums for scan

__constant__ int c_off[9] = {0, 119, 124, 136, 148, 158, 164, 170, 172};

// ---------------------------------------------------------------------------
// CSR build
__global__ void count_zero_kernel() {
    int i = blockIdx.x * blockDim.x + threadIdx.x;
    if (i < NN) { g_cnti[i] = 0; g_cur[i] = 0; }
}

__global__ void count_kernel(const int* __restrict__ dst) {
    int e = blockIdx.x * blockDim.x + threadIdx.x;
    if (e < EE) atomicAdd(&g_cnti[dst[e]], 1);
}

__global__ void blocksum_kernel() {        // NB blocks x SCAN_B threads
    __shared__ int s[SCAN_B];
    const int n = blockIdx.x * SCAN_B + threadIdx.x;
    s[threadIdx.x] = (n < NN) ? g_cnti[n] : 0;
    __syncthreads();
    for (int off = SCAN_B / 2; off > 0; off >>= 1) {
        if (threadIdx.x < off) s[threadIdx.x] += s[threadIdx.x + off];
        __syncthreads();
    }
    if (threadIdx.x == 0) g_bsum[blockIdx.x] = s[0];
}

__global__ void scanblock_kernel() {       // 1 block x 256 threads, NB<=256
    __shared__ int s[256];
    const int t = threadIdx.x;
    const int v = (t < NB) ? g_bsum[t] : 0;
    s[t] = v;
    __syncthreads();
    for (int off = 1; off < 256; off <<= 1) {
        int u = (t >= off) ? s[t - off] : 0;
        __syncthreads();
        s[t] += u;
        __syncthreads();
    }
    if (t < NB) g_bsum[t] = s[t] - v;       // exclusive
}

__global__ void rowstart_kernel() {        // NB blocks x SCAN_B threads
    __shared__ int s[SCAN_B];
    const int t = threadIdx.x;
    const int n = blockIdx.x * SCAN_B + t;
    const int v = (n < NN) ? g_cnti[n] : 0;
    s[t] = v;
    __syncthreads();
    for (int off = 1; off < SCAN_B; off <<= 1) {
        int u = (t >= off) ? s[t - off] : 0;
        __syncthreads();
        s[t] += u;
        __syncthreads();
    }
    if (n < NN) {
        g_rs[n] = s[t] - v + g_bsum[blockIdx.x];           // exclusive prefix
        g_deg[n] = rsqrtf((float)v + 1.0f);                // dinv (self-loop)
    }
    if (blockIdx.x == 0 && t == 0) g_rs[NN] = EE;
}

__global__ void fill_kernel(const int* __restrict__ src, const int* __restrict__ dst) {
    int e = blockIdx.x * blockDim.x + threadIdx.x;
    if (e >= EE) return;
    const int d = dst[e];
    const int pos = g_rs[d] + atomicAdd(&g_cur[d], 1);
    g_csr[pos] = src[e];
}

// ---------------------------------------------------------------------------
// AtomEncoder: h[n] = sum_f emb[x[n,f]+off[f]]
__global__ void embed_kernel(const int* __restrict__ x, const float* __restrict__ emb) {
    int n = blockIdx.x;
    int t = threadIdx.x;
    __shared__ int xi[9];
    if (t < 9) xi[t] = x[n * 9 + t] + c_off[t];
    __syncthreads();
    float v = 0.0f;
#pragma unroll
    for (int f = 0; f < 9; f++) v += emb[(size_t)xi[f] * HH + t];
    g_h[(size_t)n * HH + t] = v;
}

// ---------------------------------------------------------------------------
// Persistent GEMM: K-pair packed f32x2, 512 threads, 4 rows x 8 cols / thread.
// MODE 0: layer. Epilogue stores ONLY T'[r] = dinv[r] * (A@B)[r].
// MODE 2: final. Epilogue: OUT = (A@B)/max(cnt,1) + bias.
template <int MODE>
__global__ void __launch_bounds__(512, 1)
gemm_kernel(const float* __restrict__ A, const float* __restrict__ B,
            const float* __restrict__ bias, float* __restrict__ T,
            float* __restrict__ OUT, int M, int numTiles) {
    extern __shared__ float sm[];
    const int tid = threadIdx.x;              // 512 threads
    const int tx = tid & 15;                  // 16 col groups
    const int ty = tid >> 4;                  // 32 row groups
    const int r0t = ty << 2;                  // 4 rows / thread

    // Stage first A tile into buffer 0 (async).
    int tile = blockIdx.x;
    {
        const int row0 = tile * 128;
        float* dst = sm + 16384;
#pragma unroll
        for (int i = tid; i < 4096; i += 512) {
            const int r = i >> 5, c = (i & 31) << 2;
            const int gr = row0 + r;
            const float* gp = (gr < M) ? (A + (size_t)gr * HH + c) : A;
            const int sz = (gr < M) ? 16 : 0;
            const unsigned int d = (unsigned int)__cvta_generic_to_shared(&dst[r * 128 + c]);
            asm volatile("cp.async.cg.shared.global [%0], [%1], 16, %2;"
                         :: "r"(d), "l"(gp), "r"(sz));
        }
        asm volatile("cp.async.commit_group;");
    }

    // Build Bp (k-pair interleave of B), overlapping the A load.
    {
        float2* Bp = (float2*)sm;
#pragma unroll
        for (int i = tid; i < 8192; i += 512) {
            const int kk = i >> 7, c = i & 127;
            Bp[i] = make_float2(B[(2 * kk) * 128 + c], B[(2 * kk + 1) * 128 + c]);
        }
    }

    float bsv[8];
    if (MODE == 2) {
#pragma unroll
        for (int q = 0; q < 4; q++) {
            const float2 b2 = *(const float2*)&bias[32 * q + 2 * tx];
            bsv[2 * q] = b2.x; bsv[2 * q + 1] = b2.y;
        }
    }

    asm volatile("cp.async.wait_group 0;");
    __syncthreads();

    int buf = 0;
    const unsigned long long* BpU = (const unsigned long long*)sm;

    for (; tile < numTiles; tile += gridDim.x) {
        const int next = tile + gridDim.x;
        if (next < numTiles) {
            const int row0n = next * 128;
            float* dst = sm + 16384 + ((buf ^ 1) << 14);
#pragma unroll
            for (int i = tid; i < 4096; i += 512) {
                const int r = i >> 5, c = (i & 31) << 2;
                const int gr = row0n + r;
                const float* gp = (gr < M) ? (A + (size_t)gr * HH + c) : A;
                const int sz = (gr < M) ? 16 : 0;
                const unsigned int d = (unsigned int)__cvta_generic_to_shared(&dst[r * 128 + c]);
                asm volatile("cp.async.cg.shared.global [%0], [%1], 16, %2;"
                             :: "r"(d), "l"(gp), "r"(sz));
            }
            asm volatile("cp.async.commit_group;");
        }

        const float* As = sm + 16384 + (buf << 14);
        unsigned long long acc[4][8];
#pragma unroll
        for (int i = 0; i < 4; i++)
#pragma unroll
            for (int j = 0; j < 8; j++) acc[i][j] = 0ull;

#pragma unroll 2
        for (int kk = 0; kk < 64; kk++) {
            unsigned long long y[8];
            {
                const unsigned long long* yb = BpU + kk * 128 + 2 * tx;
                const ulonglong2 t0 = *(const ulonglong2*)(yb);
                const ulonglong2 t1 = *(const ulonglong2*)(yb + 32);
                const ulonglong2 t2 = *(const ulonglong2*)(yb + 64);
                const ulonglong2 t3 = *(const ulonglong2*)(yb + 96);
                y[0] = t0.x; y[1] = t0.y; y[2] = t1.x; y[3] = t1.y;
                y[4] = t2.x; y[5] = t2.y; y[6] = t3.x; y[7] = t3.y;
            }
#pragma unroll
            for (int i = 0; i < 4; i++) {
                const unsigned long long x =
                    *(const unsigned long long*)(As + (r0t + i) * 128 + 2 * kk);
#pragma unroll
                for (int j = 0; j < 8; j++)
                    asm("fma.rn.f32x2 %0, %1, %2, %0;" : "+l"(acc[i][j]) : "l"(x), "l"(y[j]));
            }
        }

        const int row0 = tile * 128;
#pragma unroll
        for (int i = 0; i < 4; i++) {
            const int r = row0 + r0t + i;
            if (r >= M) continue;
            float vv[8];
#pragma unroll
            for (int j = 0; j < 8; j++) {
                float lo, hi;
                asm("mov.b64 {%0, %1}, %2;" : "=f"(lo), "=f"(hi) : "l"(acc[i][j]));
                vv[j] = lo + hi;
            }
            if (MODE == 2) {
                const float s = 1.0f / fmaxf(g_cnt[r], 1.0f);
#pragma unroll
                for (int q = 0; q < 4; q++) {
                    float2 o;
                    o.x = fmaf(s, vv[2 * q], bsv[2 * q]);
                    o.y = fmaf(s, vv[2 * q + 1], bsv[2 * q + 1]);
                    *(float2*)&OUT[(size_t)r * TT + 32 * q + 2 * tx] = o;
                }
            } else {
                const float d = g_deg[r];   // dinv
#pragma unroll
                for (int q = 0; q < 4; q++) {
                    float2 t2;
                    t2.x = d * vv[2 * q];
                    t2.y = d * vv[2 * q + 1];
                    *(float2*)&T[(size_t)r * HH + 32 * q + 2 * tx] = t2;
                }
            }
        }

        asm volatile("cp.async.wait_group 0;");
        __syncthreads();
        buf ^= 1;
    }
}

// ---------------------------------------------------------------------------
// Aggregator: one warp / node.  OUT[n] = dinv_n * (sum_{s->n} T'[s] + T'[n]) + bias
// RELU: apply relu on write (layers 1,2 feed relu'd input to the next GEMM).
template <bool RELU>
__global__ void agg_kernel(const float* __restrict__ Tp, const float* __restrict__ bias,
                           float* __restrict__ OUT) {
    const int n = (blockIdx.x * blockDim.x + threadIdx.x) >> 5;
    const int lane = threadIdx.x & 31;
    if (n >= NN) return;
    const int c = lane << 2;

    float4 acc = *(const float4*)(Tp + (size_t)n * HH + c);   // self term
    int i = g_rs[n];
    const int end = g_rs[n + 1];
    for (; i + 1 < end; i += 2) {
        const int s0 = g_csr[i];
        const int s1 = g_csr[i + 1];
        const float4 v0 = *(const float4*)(Tp + (size_t)s0 * HH + c);
        const float4 v1 = *(const float4*)(Tp + (size_t)s1 * HH + c);
        acc.x += v0.x; acc.y += v0.y; acc.z += v0.z; acc.w += v0.w;
        acc.x += v1.x; acc.y += v1.y; acc.z += v1.z; acc.w += v1.w;
    }
    if (i < end) {
        const int s0 = g_csr[i];
        const float4 v0 = *(const float4*)(Tp + (size_t)s0 * HH + c);
        acc.x += v0.x; acc.y += v0.y; acc.z += v0.z; acc.w += v0.w;
    }

    const float d = g_deg[n];
    const float4 b = *(const float4*)(bias + c);
    float4 o;
    o.x = fmaf(d, acc.x, b.x);
    o.y = fmaf(d, acc.y, b.y);
    o.z = fmaf(d, acc.z, b.z);
    o.w = fmaf(d, acc.w, b.w);
    if (RELU) {
        o.x = fmaxf(o.x, 0.f); o.y = fmaxf(o.y, 0.f);
        o.z = fmaxf(o.z, 0.f); o.w = fmaxf(o.w, 0.f);
    }
    *(float4*)(OUT + (size_t)n * HH + c) = o;
}

// ---------------------------------------------------------------------------
__global__ void pool_zero_kernel() {
    int i = blockIdx.x * blockDim.x + threadIdx.x;
    if (i < GG * HH) g_pool[i] = 0.0f;
    if (i < GG) g_cnt[i] = 0.0f;
}

// one warp / node: pooled[batch[n]] += h[n]; cnt[batch[n]] += 1
__global__ void pool_scatter_kernel(const int* __restrict__ batch, const float* __restrict__ h) {
    const int n = (blockIdx.x * blockDim.x + threadIdx.x) >> 5;
    const int lane = threadIdx.x & 31;
    if (n >= NN) return;
    const int g = batch[n];
    float4 v = *(const float4*)(h + (size_t)n * HH + (lane << 2));
    float* p = g_pool + (size_t)g * HH + (lane << 2);
    asm volatile("red.global.add.v4.f32 [%0], {%1,%2,%3,%4};"
                 :: "l"(p), "f"(v.x), "f"(v.y), "f"(v.z), "f"(v.w)
                 : "memory");
    if (lane == 0) atomicAdd(&g_cnt[g], 1.0f);
}

// ---------------------------------------------------------------------------
extern "C" void kernel_launch(void* const* d_in, const int* in_sizes, int n_in,
                              void* d_out, int out_size) {
    const int*   x     = (const int*)d_in[0];
    const int*   ei    = (const int*)d_in[1];
    const int*   batch = (const int*)d_in[2];
    const float* emb   = (const float*)d_in[3];
    const float* W1    = (const float*)d_in[4];
    const float* b1    = (const float*)d_in[5];
    const float* W2    = (const float*)d_in[6];
    const float* b2    = (const float*)d_in[7];
    const float* W3    = (const float*)d_in[8];
    const float* b3    = (const float*)d_in[9];
    const float* Wl    = (const float*)d_in[10];
    const float* bl    = (const float*)d_in[11];
    float* out = (float*)d_out;

    const int* srcp = ei;
    const int* dstp = ei + EE;

    float *p_h, *p_t, *p_o, *p_pool;
    cudaGetSymbolAddress((void**)&p_h, g_h);
    cudaGetSymbolAddress((void**)&p_t, g_t);
    cudaGetSymbolAddress((void**)&p_o, g_o);
    cudaGetSymbolAddress((void**)&p_pool, g_pool);

    const int SMEM = 3 * 128 * 128 * (int)sizeof(float);   // 192KB: Bp + 2x A buffers
    static bool attr_set = false;
    if (!attr_set) {
        cudaFuncSetAttribute(gemm_kernel<0>, cudaFuncAttributeMaxDynamicSharedMemorySize, SMEM);
        cudaFuncSetAttribute(gemm_kernel<2>, cudaFuncAttributeMaxDynamicSharedMemorySize, SMEM);
        attr_set = true;
    }

    // ---- CSR build (also computes dinv) ----
    count_zero_kernel<<<(NN + 255) / 256, 256>>>();
    count_kernel<<<(EE + 255) / 256, 256>>>(dstp);
    blocksum_kernel<<<NB, SCAN_B>>>();
    scanblock_kernel<<<1, 256>>>();
    rowstart_kernel<<<NB, SCAN_B>>>();
    fill_kernel<<<(EE + 255) / 256, 256>>>(srcp, dstp);

    // atom embedding sum
    embed_kernel<<<NN, 128>>>(x, emb);

    const int tilesN = (NN + 127) / 128;      // 782
    const int tilesG = (GG + 127) / 128;      // 32
    const int gridN = tilesN < 148 ? tilesN : 148;
    const int gridG = tilesG < 148 ? tilesG : 148;
    const int agg_blocks = (NN * 32 + 255) / 256;

    // Layer 1: t' = dinv*(h@W1); o = relu(agg(t') + b1)
    gemm_kernel<0><<<gridN, 512, SMEM>>>(p_h, W1, nullptr, p_t, nullptr, NN, tilesN);
    agg_kernel<true><<<agg_blocks, 256>>>(p_t, b1, p_o);

    // Layer 2: t' = dinv*(o@W2); h = relu(agg(t') + b2)
    gemm_kernel<0><<<gridN, 512, SMEM>>>(p_o, W2, nullptr, p_t, nullptr, NN, tilesN);
    agg_kernel<true><<<agg_blocks, 256>>>(p_t, b2, p_h);

    // Layer 3: t' = dinv*(h@W3); o = agg(t') + b3   (no relu)
    gemm_kernel<0><<<gridN, 512, SMEM>>>(p_h, W3, nullptr, p_t, nullptr, NN, tilesN);
    agg_kernel<false><<<agg_blocks, 256>>>(p_t, b3, p_o);

    // Mean pool + final linear
    pool_zero_kernel<<<(GG * HH + 255) / 256, 256>>>();
    pool_scatter_kernel<<<(NN * 32 + 255) / 256, 256>>>(batch, p_o);
    gemm_kernel<2><<<gridG, 512, SMEM>>>(p_pool, Wl, bl, nullptr, out, GG, tilesG);
}